// round 15
// baseline (speedup 1.0000x reference)
#include <cuda_runtime.h>
#include <cuda_fp16.h>
#include <cstdint>

// SparseWindowedAttention: B=1, S=4096, E=768, H=12, hd=64, window=128
// R15: BK=32 -> BK=64 in both GEMMs (rows fully packed, chunk count and
//      syncs halved; same smem, same occupancy, bit-identical math).
//      Attention/prep = R14 (validated).

#define S_LEN 4096
#define EDIM  768
#define NH    12
#define HD    64
#define QKVN  2304
#define WIN   128

// ------------------------- scratch -------------------------
__device__ __half g_xhi[(size_t)S_LEN * EDIM];
__device__ __half g_wqh[(size_t)QKVN * EDIM];   // row-permuted: [Q|K|V]
__device__ __half g_woh[(size_t)EDIM * EDIM];
__device__ float  g_bqp[QKVN];
__device__ __half g_qkvhi[(size_t)S_LEN * QKVN];
__device__ __half g_ahi[(size_t)S_LEN * EDIM];

// ------------------------- helpers -------------------------
__device__ __forceinline__ uint32_t smem_u32(const void* p) {
    uint32_t a;
    asm("{ .reg .u64 t; cvta.to.shared.u64 t, %1; cvt.u32.u64 %0, t; }" : "=r"(a) : "l"(p));
    return a;
}

#define CP_ASYNC16(saddr, gptr) \
    asm volatile("cp.async.cg.shared.global [%0], [%1], 16;" :: "r"(saddr), "l"(gptr))
#define CP_ASYNC16Z(saddr, gptr, sz) \
    asm volatile("cp.async.cg.shared.global [%0], [%1], 16, %2;" :: "r"(saddr), "l"(gptr), "r"(sz))
#define CP_COMMIT() asm volatile("cp.async.commit_group;")
#define CP_WAIT1()  asm volatile("cp.async.wait_group 1;")
#define CP_WAIT0()  asm volatile("cp.async.wait_group 0;")

__device__ __forceinline__ void ldsm_x4(uint32_t* r, uint32_t addr) {
    asm volatile("ldmatrix.sync.aligned.m8n8.x4.shared.b16 {%0,%1,%2,%3}, [%4];"
                 : "=r"(r[0]), "=r"(r[1]), "=r"(r[2]), "=r"(r[3]) : "r"(addr));
}
__device__ __forceinline__ void ldsm_x2(uint32_t* r, uint32_t addr) {
    asm volatile("ldmatrix.sync.aligned.m8n8.x2.shared.b16 {%0,%1}, [%2];"
                 : "=r"(r[0]), "=r"(r[1]) : "r"(addr));
}
__device__ __forceinline__ void ldsm_x2_trans(uint32_t* r, uint32_t addr) {
    asm volatile("ldmatrix.sync.aligned.m8n8.x2.trans.shared.b16 {%0,%1}, [%2];"
                 : "=r"(r[0]), "=r"(r[1]) : "r"(addr));
}
__device__ __forceinline__ void mma_f16(float* d, const uint32_t* a, const uint32_t* b) {
    asm volatile(
        "mma.sync.aligned.m16n8k16.row.col.f32.f16.f16.f32 "
        "{%0,%1,%2,%3}, {%4,%5,%6,%7}, {%8,%9}, {%0,%1,%2,%3};"
        : "+f"(d[0]), "+f"(d[1]), "+f"(d[2]), "+f"(d[3])
        : "r"(a[0]), "r"(a[1]), "r"(a[2]), "r"(a[3]), "r"(b[0]), "r"(b[1]));
}

__device__ __forceinline__ void split2h(float x, float y, uint32_t& hi, uint32_t& lo) {
    __half hx = __float2half_rn(x);
    __half hy = __float2half_rn(y);
    __half lx = __float2half_rn(x - __half2float(hx));
    __half ly = __float2half_rn(y - __half2float(hy));
    hi = ((uint32_t)__half_as_ushort(hy) << 16) | (uint32_t)__half_as_ushort(hx);
    lo = ((uint32_t)__half_as_ushort(ly) << 16) | (uint32_t)__half_as_ushort(lx);
}

// ---------------------------------------------------------------------------
// merged preprocessing (R14 verbatim)
// ---------------------------------------------------------------------------
#define NX4  ((S_LEN * EDIM) / 4)
#define NWQ4 ((QKVN * EDIM) / 4)
#define NWO4 ((EDIM * EDIM) / 4)
#define R4   (EDIM / 4)

__global__ void prep_kernel(const float4* __restrict__ x, __half2* __restrict__ xhi,
                            const float4* __restrict__ wq, __half2* __restrict__ wqh,
                            const float4* __restrict__ wo, __half2* __restrict__ woh,
                            const float* __restrict__ bq, float* __restrict__ bqp)
{
    int i = blockIdx.x * blockDim.x + threadIdx.x;
    if (i < NX4) {
        float4 v = x[i];
        xhi[2*i]   = __floats2half2_rn(v.x, v.y);
        xhi[2*i+1] = __floats2half2_rn(v.z, v.w);
    } else if (i < NX4 + NWQ4) {
        int j = i - NX4;
        int c = j / R4;
        int ic = j % R4;
        int h = c / 192, t = (c % 192) / 64, d = c % 64;
        int cp = t * EDIM + h * 64 + d;
        float4 v = wq[j];
        int o = cp * R4 + ic;
        wqh[2*o]   = __floats2half2_rn(v.x, v.y);
        wqh[2*o+1] = __floats2half2_rn(v.z, v.w);
    } else if (i < NX4 + NWQ4 + NWO4) {
        int j = i - NX4 - NWQ4;
        float4 v = wo[j];
        woh[2*j]   = __floats2half2_rn(v.x, v.y);
        woh[2*j+1] = __floats2half2_rn(v.z, v.w);
    } else if (i < NX4 + NWQ4 + NWO4 + QKVN) {
        int c = i - NX4 - NWQ4 - NWO4;
        int h = c / 192, t = (c % 192) / 64, d = c % 64;
        bqp[t * EDIM + h * 64 + d] = bq[c];
    }
}

// ---------------------------------------------------------------------------
// GEMM1 (1-pass, BK=64): qkv = x_hi @ W_hi^T + bias. 128x128 CTA, 8 warps,
// warp 64x32. Stage = A 16KB | B 16KB (full 128B rows), 3 stages, 12 chunks.
// ---------------------------------------------------------------------------
#define TILE_BYTES 16384
#define STAGE_BYTES (2 * TILE_BYTES)
#define NSTAGE 3
#define GEMM_SMEM (NSTAGE * STAGE_BYTES + 1024)

__global__ __launch_bounds__(256, 2) void gemm_tc_kernel(
    const __half* __restrict__ Ahi,
    const __half* __restrict__ Bhi,
    const float* __restrict__ bias,
    __half* __restrict__ Chi,
    int M, int N, int K)
{
    extern __shared__ char smem[];
    const uint32_t sraw = smem_u32(smem);
    const uint32_t sbase = (sraw + 1023u) & ~1023u;

    const int tid  = threadIdx.x;
    const int wid  = tid >> 5;
    const int lane = tid & 31;
    const int bm = blockIdx.y * 128;
    const int bn = blockIdx.x * 128;
    const int nch = K >> 6;             // BK=64

    const int warp_m = wid & 1;
    const int warp_n = wid >> 1;

    // loader: 2 threads/row, 4x16B chunks each per tile (full 128B rows)
    const int lrow = tid >> 1;
    const int lsel = tid & 1;
    const uint32_t lsw = (uint32_t)((lrow & 7) << 4);
    const uint32_t lrowbase = (uint32_t)lrow * 128;
    uint32_t lofs[4];
    #pragma unroll
    for (int j = 0; j < 4; j++)
        lofs[j] = ((uint32_t)(lsel * 64 + j * 16)) ^ lsw;

    const __half* gah = Ahi + (size_t)(bm + lrow) * K + lsel * 32;
    const __half* gbh = Bhi + (size_t)(bn + lrow) * K + lsel * 32;

    float acc[4][4][4];
    #pragma unroll
    for (int i = 0; i < 4; i++)
        #pragma unroll
        for (int j = 0; j < 4; j++)
            #pragma unroll
            for (int e = 0; e < 4; e++) acc[i][j][e] = 0.f;

    auto load_stage = [&](int t, int buf) {
        const uint32_t sA = sbase + buf * STAGE_BYTES + lrowbase;
        const uint32_t sB = sA + TILE_BYTES;
        const int k0 = t * 64;
        #pragma unroll
        for (int j = 0; j < 4; j++) {
            CP_ASYNC16(sA + lofs[j], gah + k0 + j * 8);
            CP_ASYNC16(sB + lofs[j], gbh + k0 + j * 8);
        }
    };

    load_stage(0, 0); CP_COMMIT();
    load_stage(1, 1); CP_COMMIT();

    const int la_row = lane & 15;
    const int la_kh  = lane >> 4;
    const int lb_row = lane & 7;
    const int lb_kh  = (lane >> 3) & 1;

    uint32_t a_rowbase[4], a_sw[4];
    #pragma unroll
    for (int mi = 0; mi < 4; mi++) {
        const int row = warp_m * 64 + mi * 16 + la_row;
        a_rowbase[mi] = (uint32_t)row * 128;
        a_sw[mi] = (uint32_t)((row & 7) << 4);
    }
    uint32_t b_rowbase[4], b_sw[4];
    #pragma unroll
    for (int ni = 0; ni < 4; ni++) {
        const int row = warp_n * 32 + ni * 8 + lb_row;
        b_rowbase[ni] = (uint32_t)row * 128;
        b_sw[ni] = (uint32_t)((row & 7) << 4);
    }

    int buf = 0;
    for (int t = 0; t < nch; t++) {
        CP_WAIT1();
        __syncthreads();
        if (t + 2 < nch) {
            int b2 = buf + 2; if (b2 >= NSTAGE) b2 -= NSTAGE;
            load_stage(t + 2, b2);
        }
        CP_COMMIT();

        const uint32_t sA = sbase + buf * STAGE_BYTES;
        const uint32_t sB = sA + TILE_BYTES;

        #pragma unroll
        for (int ks = 0; ks < 4; ks++) {
            const uint32_t akoff = (uint32_t)(ks * 32 + la_kh * 16);
            const uint32_t bkoff = (uint32_t)(ks * 32 + lb_kh * 16);
            uint32_t bhv[4][2];
            #pragma unroll
            for (int ni = 0; ni < 4; ni++)
                ldsm_x2(bhv[ni], sB + b_rowbase[ni] + (bkoff ^ b_sw[ni]));
            #pragma unroll
            for (int mi = 0; mi < 4; mi++) {
                uint32_t ahi[4];
                ldsm_x4(ahi, sA + a_rowbase[mi] + (akoff ^ a_sw[mi]));
                #pragma unroll
                for (int ni = 0; ni < 4; ni++)
                    mma_f16(acc[mi][ni], ahi, bhv[ni]);
            }
        }
        buf++; if (buf >= NSTAGE) buf = 0;
    }

    #pragma unroll
    for (int mi = 0; mi < 4; mi++) {
        const int row = bm + warp_m * 64 + mi * 16 + (lane >> 2);
        #pragma unroll
        for (int ni = 0; ni < 4; ni++) {
            const int col = bn + warp_n * 32 + ni * 8 + (lane & 3) * 2;
            const float2 bv = *(const float2*)(bias + col);
            __half2 h0 = __floats2half2_rn(acc[mi][ni][0] + bv.x, acc[mi][ni][1] + bv.y);
            __half2 h1 = __floats2half2_rn(acc[mi][ni][2] + bv.x, acc[mi][ni][3] + bv.y);
            *(__half2*)(Chi + (size_t)row * N + col)       = h0;
            *(__half2*)(Chi + (size_t)(row + 8) * N + col) = h1;
        }
    }
}

// ---------------------------------------------------------------------------
// GEMM2 (1-pass, BK=64): 64x128 CTA tile, 8 warps, warp 32x32.
// Stage = A 8KB | B 16KB (full 128B rows), 3 stages, 12 chunks.
// ---------------------------------------------------------------------------
#define G2_A_BYTES 8192
#define G2_STAGE   24576
#define G2_SMEM    (3 * G2_STAGE + 1024)

__global__ __launch_bounds__(256, 2) void gemm2_tc_kernel(
    const __half* __restrict__ Ahi,
    const __half* __restrict__ Bhi,
    const float* __restrict__ bias, float* __restrict__ C,
    int M, int N, int K)
{
    extern __shared__ char smem[];
    const uint32_t sraw = smem_u32(smem);
    const uint32_t sbase = (sraw + 1023u) & ~1023u;

    const int tid  = threadIdx.x;
    const int wid  = tid >> 5;
    const int lane = tid & 31;
    const int bm = blockIdx.y * 64;
    const int bn = blockIdx.x * 128;
    const int nch = K >> 6;

    const int warp_m = wid & 1;
    const int warp_n = wid >> 1;

    // A loader: 4 threads/row over 64 rows, 2 chunks each
    const int arow = tid >> 2;
    const int ac   = tid & 3;
    const uint32_t asw = (uint32_t)((arow & 7) << 4);
    const uint32_t arowbase = (uint32_t)arow * 128;
    uint32_t aofs[2];
    #pragma unroll
    for (int j = 0; j < 2; j++)
        aofs[j] = ((uint32_t)(ac * 32 + j * 16)) ^ asw;
    const __half* gah = Ahi + (size_t)(bm + arow) * K + ac * 16;

    // B loader: 2 threads/row over 128 rows, 4 chunks each
    const int brow = tid >> 1;
    const int bc   = tid & 1;
    const uint32_t bsw = (uint32_t)((brow & 7) << 4);
    const uint32_t browbase = (uint32_t)brow * 128;
    uint32_t bofs[4];
    #pragma unroll
    for (int j = 0; j < 4; j++)
        bofs[j] = ((uint32_t)(bc * 64 + j * 16)) ^ bsw;
    const __half* gbh = Bhi + (size_t)(bn + brow) * K + bc * 32;

    float acc[2][4][4];
    #pragma unroll
    for (int i = 0; i < 2; i++)
        #pragma unroll
        for (int j = 0; j < 4; j++)
            #pragma unroll
            for (int e = 0; e < 4; e++) acc[i][j][e] = 0.f;

    auto load_stage = [&](int t, int buf) {
        const int k0 = t * 64;
        const uint32_t sA = sbase + buf * G2_STAGE + arowbase;
        const uint32_t sB = sbase + buf * G2_STAGE + G2_A_BYTES + browbase;
        #pragma unroll
        for (int j = 0; j < 2; j++)
            CP_ASYNC16(sA + aofs[j], gah + k0 + j * 8);
        #pragma unroll
        for (int j = 0; j < 4; j++)
            CP_ASYNC16(sB + bofs[j], gbh + k0 + j * 8);
    };

    load_stage(0, 0); CP_COMMIT();
    load_stage(1, 1); CP_COMMIT();

    const int la_row = lane & 15;
    const int la_kh  = lane >> 4;
    const int lb_row = lane & 7;
    const int lb_kh  = (lane >> 3) & 1;

    uint32_t a_rowbase[2], a_sw2[2];
    #pragma unroll
    for (int mi = 0; mi < 2; mi++) {
        const int row = warp_m * 32 + mi * 16 + la_row;
        a_rowbase[mi] = (uint32_t)row * 128;
        a_sw2[mi] = (uint32_t)((row & 7) << 4);
    }
    uint32_t b_rowbase[4], b_sw2[4];
    #pragma unroll
    for (int ni = 0; ni < 4; ni++) {
        const int row = warp_n * 32 + ni * 8 + lb_row;
        b_rowbase[ni] = (uint32_t)(G2_A_BYTES + row * 128);
        b_sw2[ni] = (uint32_t)((row & 7) << 4);
    }

    int buf = 0;
    for (int t = 0; t < nch; t++) {
        CP_WAIT1();
        __syncthreads();
        if (t + 2 < nch) {
            int b2 = buf + 2; if (b2 >= 3) b2 -= 3;
            load_stage(t + 2, b2);
        }
        CP_COMMIT();

        const uint32_t sS = sbase + buf * G2_STAGE;

        #pragma unroll
        for (int ks = 0; ks < 4; ks++) {
            const uint32_t akoff = (uint32_t)(ks * 32 + la_kh * 16);
            const uint32_t bkoff = (uint32_t)(ks * 32 + lb_kh * 16);
            uint32_t bhv[4][2];
            #pragma unroll
            for (int ni = 0; ni < 4; ni++)
                ldsm_x2(bhv[ni], sS + b_rowbase[ni] + (bkoff ^ b_sw2[ni]));
            #pragma unroll
            for (int mi = 0; mi < 2; mi++) {
                uint32_t ahi[4];
                ldsm_x4(ahi, sS + a_rowbase[mi] + (akoff ^ a_sw2[mi]));
                #pragma unroll
                for (int ni = 0; ni < 4; ni++)
                    mma_f16(acc[mi][ni], ahi, bhv[ni]);
            }
        }
        buf++; if (buf >= 3) buf = 0;
    }

    #pragma unroll
    for (int mi = 0; mi < 2; mi++) {
        const int row = bm + warp_m * 32 + mi * 16 + (lane >> 2);
        #pragma unroll
        for (int ni = 0; ni < 4; ni++) {
            const int col = bn + warp_n * 32 + ni * 8 + (lane & 3) * 2;
            const float2 bv = *(const float2*)(bias + col);
            *(float2*)(C + (size_t)row * N + col) =
                make_float2(acc[mi][ni][0] + bv.x, acc[mi][ni][1] + bv.y);
            *(float2*)(C + (size_t)(row + 8) * N + col) =
                make_float2(acc[mi][ni][2] + bv.x, acc[mi][ni][3] + bv.y);
        }
    }
}

// ---------------------------------------------------------------------------
// Flash attention (R14 verbatim): QK 1-pass, PV 2-pass, 64-q CTA, 4 warps,
// cp.async double-buffered K/V prefetch.
// ---------------------------------------------------------------------------
#define QPITCH 72
#define SQHI 0
#define SKV0 9216
#define KVBUF 18432
#define ATTN_SMEM 46080

__global__ __launch_bounds__(128) void attn_tc_kernel(
    const __half* __restrict__ qkvhi, __half* __restrict__ ahi)
{
    extern __shared__ char smem[];
    const uint32_t sb = smem_u32(smem);

    const int tid  = threadIdx.x;
    const int lane = tid & 31;
    const int wq   = tid >> 5;
    const int h    = blockIdx.y;
    const int q0   = blockIdx.x * 64;

    const int lrow = tid >> 1;
    const int half = tid & 1;
    const uint32_t soff = (uint32_t)(lrow * QPITCH + half * 32) * 2;

    {
        const __half* sh = qkvhi + (size_t)(q0 + lrow) * QKVN + h * 64 + half * 32;
        #pragma unroll
        for (int i = 0; i < 4; i++)
            *(uint4*)(smem + SQHI + soff + i * 16) = *(const uint4*)(sh + i * 8);
    }

    auto kv_load = [&](int kb, int buf) {
        const int g = q0 - WIN + kb * 64 + lrow;
        const bool v = (g >= 0) && (g < S_LEN);
        const size_t gb = (size_t)(v ? g : 0) * QKVN + 768 + h * 64 + half * 32;
        const unsigned sz = v ? 16u : 0u;
        const uint32_t sk = sb + SKV0 + (uint32_t)buf * KVBUF + soff;
        const uint32_t sv = sk + 9216;
        #pragma unroll
        for (int i = 0; i < 4; i++) {
            CP_ASYNC16Z(sk + i * 16, qkvhi + gb + i * 8, sz);
            CP_ASYNC16Z(sv + i * 16, qkvhi + gb + 768 + i * 8, sz);
        }
    };

    kv_load(0, 0); CP_COMMIT();

    float oacc[8][4];
    #pragma unroll
    for (int ni = 0; ni < 8; ni++)
        #pragma unroll
        for (int e = 0; e < 4; e++) oacc[ni][e] = 0.f;
    float m_a = -1e30f, m_b = -1e30f, l_a = 0.f, l_b = 0.f;

    const int ra = q0 + wq * 16 + (lane >> 2);
    const int rb = ra + 8;

    for (int kb = 0; kb < 5; kb++) {
        const int jbase = q0 - WIN + kb * 64;
        if (kb + 1 < 5) {
            kv_load(kb + 1, (kb + 1) & 1);
            CP_COMMIT();
            CP_WAIT1();
        } else {
            CP_WAIT0();
        }
        __syncthreads();

        const uint32_t sk = sb + SKV0 + (uint32_t)(kb & 1) * KVBUF;
        const uint32_t sv = sk + 9216;

        float sacc[8][4];
        #pragma unroll
        for (int ni = 0; ni < 8; ni++)
            #pragma unroll
            for (int e = 0; e < 4; e++) sacc[ni][e] = 0.f;

        #pragma unroll
        for (int ks = 0; ks < 4; ks++) {
            uint32_t aqh[4];
            const uint32_t qoff = (uint32_t)((wq*16 + (lane & 15)) * QPITCH + ks*16 + (lane >> 4) * 8) * 2;
            ldsm_x4(aqh, sb + SQHI + qoff);
            #pragma unroll
            for (int ni = 0; ni < 8; ni++) {
                uint32_t bh[2];
                const uint32_t koff = (uint32_t)((ni*8 + (lane & 7)) * QPITCH + ks*16 + ((lane >> 3) & 1) * 8) * 2;
                ldsm_x2(bh, sk + koff);
                mma_f16(sacc[ni], aqh, bh);
            }
        }

        float mk_a = -1e30f, mk_b = -1e30f;
        #pragma unroll
        for (int ni = 0; ni < 8; ni++) {
            const int j0 = jbase + ni * 8 + (lane & 3) * 2;
            #pragma unroll
            for (int e = 0; e < 4; e++) {
                const int g = j0 + (e & 1);
                const int r = (e < 2) ? ra : rb;
                const int d = r - g;
                const bool ok = (g >= 0) && (g < S_LEN) && (d <= WIN) && (d >= -WIN);
                const float s = ok ? sacc[ni][e] * 0.125f : -1e30f;
                sacc[ni][e] = s;
                if (e < 2) mk_a = fmaxf(mk_a, s); else mk_b = fmaxf(mk_b, s);
            }
        }
        mk_a = fmaxf(mk_a, __shfl_xor_sync(0xffffffffu, mk_a, 1));
        mk_a = fmaxf(mk_a, __shfl_xor_sync(0xffffffffu, mk_a, 2));
        mk_b = fmaxf(mk_b, __shfl_xor_sync(0xffffffffu, mk_b, 1));
        mk_b = fmaxf(mk_b, __shfl_xor_sync(0xffffffffu, mk_b, 2));

        const float mn_a = fmaxf(m_a, mk_a);
        const float mn_b = fmaxf(m_b, mk_b);
        const float corr_a = __expf(m_a - mn_a);
        const float corr_b = __expf(m_b - mn_b);
        const float sm_a = (mn_a < -1e29f) ? 0.f : mn_a;
        const float sm_b = (mn_b < -1e29f) ? 0.f : mn_b;

        float su_a = 0.f, su_b = 0.f;
        #pragma unroll
        for (int ni = 0; ni < 8; ni++) {
            #pragma unroll
            for (int e = 0; e < 4; e++) {
                const float p = __expf(sacc[ni][e] - ((e < 2) ? sm_a : sm_b));
                sacc[ni][e] = p;
                if (e < 2) su_a += p; else su_b += p;
            }
        }
        su_a += __shfl_xor_sync(0xffffffffu, su_a, 1);
        su_a += __shfl_xor_sync(0xffffffffu, su_a, 2);
        su_b += __shfl_xor_sync(0xffffffffu, su_b, 1);
        su_b += __shfl_xor_sync(0xffffffffu, su_b, 2);

        l_a = l_a * corr_a + su_a;
        l_b = l_b * corr_b + su_b;
        m_a = mn_a; m_b = mn_b;

        #pragma unroll
        for (int ni = 0; ni < 8; ni++) {
            oacc[ni][0] *= corr_a; oacc[ni][1] *= corr_a;
            oacc[ni][2] *= corr_b; oacc[ni][3] *= corr_b;
        }

        #pragma unroll
        for (int kk = 0; kk < 4; kk++) {
            uint32_t aph[4], apl[4];
            split2h(sacc[2*kk][0],   sacc[2*kk][1],   aph[0], apl[0]);
            split2h(sacc[2*kk][2],   sacc[2*kk][3],   aph[1], apl[1]);
            split2h(sacc[2*kk+1][0], sacc[2*kk+1][1], aph[2], apl[2]);
            split2h(sacc[2*kk+1][2], sacc[2*kk+1][3], aph[3], apl[3]);
            #pragma unroll
            for (int ni = 0; ni < 8; ni++) {
                uint32_t bvh[2];
                const uint32_t voff = (uint32_t)((kk*16 + (lane & 15)) * QPITCH + ni * 8) * 2;
                ldsm_x2_trans(bvh, sv + voff);
                mma_f16(oacc[ni], aph, bvh);
                mma_f16(oacc[ni], apl, bvh);
            }
        }
        __syncthreads();
    }

    const float inv_a = (l_a > 0.f) ? 1.f / l_a : 0.f;
    const float inv_b = (l_b > 0.f) ? 1.f / l_b : 0.f;
    #pragma unroll
    for (int ni = 0; ni < 8; ni++) {
        const int d = h * 64 + ni * 8 + (lane & 3) * 2;
        __half2 o0 = __floats2half2_rn(oacc[ni][0] * inv_a, oacc[ni][1] * inv_a);
        __half2 o1 = __floats2half2_rn(oacc[ni][2] * inv_b, oacc[ni][3] * inv_b);
        *(__half2*)(ahi + (size_t)ra * EDIM + d) = o0;
        *(__half2*)(ahi + (size_t)rb * EDIM + d) = o1;
    }
}

// ---------------------------------------------------------------------------
extern "C" void kernel_launch(void* const* d_in, const int* in_sizes, int n_in,
                              void* d_out, int out_size)
{
    const float* x    = (const float*)d_in[0];
    const float* Wqkv = (const float*)d_in[1];
    const float* bqkv = (const float*)d_in[2];
    const float* Wo   = (const float*)d_in[3];
    const float* bo   = (const float*)d_in[4];
    float* out = (float*)d_out;

    __half *xhi, *wqh, *woh, *qkvhi, *ahi;
    float *bqp;
    cudaGetSymbolAddress((void**)&xhi,   g_xhi);
    cudaGetSymbolAddress((void**)&wqh,   g_wqh);
    cudaGetSymbolAddress((void**)&woh,   g_woh);
    cudaGetSymbolAddress((void**)&bqp,   g_bqp);
    cudaGetSymbolAddress((void**)&qkvhi, g_qkvhi);
    cudaGetSymbolAddress((void**)&ahi,   g_ahi);

    cudaFuncSetAttribute(gemm_tc_kernel,  cudaFuncAttributeMaxDynamicSharedMemorySize, GEMM_SMEM);
    cudaFuncSetAttribute(gemm2_tc_kernel, cudaFuncAttributeMaxDynamicSharedMemorySize, G2_SMEM);
    cudaFuncSetAttribute(attn_tc_kernel,  cudaFuncAttributeMaxDynamicSharedMemorySize, ATTN_SMEM);

    // 0) merged preprocessing
    {
        int ntot = NX4 + NWQ4 + NWO4 + QKVN;
        prep_kernel<<<(ntot + 255) / 256, 256>>>(
            (const float4*)x, (__half2*)xhi,
            (const float4*)Wqkv, (__half2*)wqh,
            (const float4*)Wo, (__half2*)woh,
            bqkv, bqp);
    }

    // 1) QKV projection (1-pass, BK=64) -> [Q|K|V] fp16
    gemm_tc_kernel<<<dim3(QKVN / 128, S_LEN / 128), 256, GEMM_SMEM>>>(
        xhi, wqh, bqp, qkvhi, S_LEN, QKVN, EDIM);

    // 2) flash attention (QK 1-pass, PV 2-pass) -> a_hi
    attn_tc_kernel<<<dim3(S_LEN / 64, NH), 128, ATTN_SMEM>>>(qkvhi, ahi);

    // 3) output projection (1-pass, BK=64) -> fp32 out
    gemm2_tc_kernel<<<dim3(EDIM / 128, S_LEN / 64), 256, G2_SMEM>>>(
        ahi, woh, bo, out, S_LEN, EDIM, EDIM);
}

// round 17
// speedup vs baseline: 1.0936x; 1.0936x over previous
#include <cuda_runtime.h>
#include <cuda_fp16.h>
#include <cstdint>

// SparseWindowedAttention: B=1, S=4096, E=768, H=12, hd=64, window=128
// R17: R16 with the compile fix (pack_h2 helper instead of nonexistent
//      __half2_as_uint). GEMMs = R14 BK=32 (validated). Attention PV 1-pass.

#define S_LEN 4096
#define EDIM  768
#define NH    12
#define HD    64
#define QKVN  2304
#define WIN   128

// ------------------------- scratch -------------------------
__device__ __half g_xhi[(size_t)S_LEN * EDIM];
__device__ __half g_wqh[(size_t)QKVN * EDIM];   // row-permuted: [Q|K|V]
__device__ __half g_woh[(size_t)EDIM * EDIM];
__device__ float  g_bqp[QKVN];
__device__ __half g_qkvhi[(size_t)S_LEN * QKVN];
__device__ __half g_ahi[(size_t)S_LEN * EDIM];

// ------------------------- helpers -------------------------
__device__ __forceinline__ uint32_t smem_u32(const void* p) {
    uint32_t a;
    asm("{ .reg .u64 t; cvta.to.shared.u64 t, %1; cvt.u32.u64 %0, t; }" : "=r"(a) : "l"(p));
    return a;
}

#define CP_ASYNC16(saddr, gptr) \
    asm volatile("cp.async.cg.shared.global [%0], [%1], 16;" :: "r"(saddr), "l"(gptr))
#define CP_ASYNC16Z(saddr, gptr, sz) \
    asm volatile("cp.async.cg.shared.global [%0], [%1], 16, %2;" :: "r"(saddr), "l"(gptr), "r"(sz))
#define CP_COMMIT() asm volatile("cp.async.commit_group;")
#define CP_WAIT1()  asm volatile("cp.async.wait_group 1;")
#define CP_WAIT0()  asm volatile("cp.async.wait_group 0;")

__device__ __forceinline__ void ldsm_x4(uint32_t* r, uint32_t addr) {
    asm volatile("ldmatrix.sync.aligned.m8n8.x4.shared.b16 {%0,%1,%2,%3}, [%4];"
                 : "=r"(r[0]), "=r"(r[1]), "=r"(r[2]), "=r"(r[3]) : "r"(addr));
}
__device__ __forceinline__ void ldsm_x2(uint32_t* r, uint32_t addr) {
    asm volatile("ldmatrix.sync.aligned.m8n8.x2.shared.b16 {%0,%1}, [%2];"
                 : "=r"(r[0]), "=r"(r[1]) : "r"(addr));
}
__device__ __forceinline__ void ldsm_x2_trans(uint32_t* r, uint32_t addr) {
    asm volatile("ldmatrix.sync.aligned.m8n8.x2.trans.shared.b16 {%0,%1}, [%2];"
                 : "=r"(r[0]), "=r"(r[1]) : "r"(addr));
}
__device__ __forceinline__ void mma_f16(float* d, const uint32_t* a, const uint32_t* b) {
    asm volatile(
        "mma.sync.aligned.m16n8k16.row.col.f32.f16.f16.f32 "
        "{%0,%1,%2,%3}, {%4,%5,%6,%7}, {%8,%9}, {%0,%1,%2,%3};"
        : "+f"(d[0]), "+f"(d[1]), "+f"(d[2]), "+f"(d[3])
        : "r"(a[0]), "r"(a[1]), "r"(a[2]), "r"(a[3]), "r"(b[0]), "r"(b[1]));
}

// pack two floats to fp16x2 in a uint32 register
__device__ __forceinline__ uint32_t pack_h2(float x, float y) {
    __half2 h = __floats2half2_rn(x, y);
    return *reinterpret_cast<uint32_t*>(&h);
}

// ---------------------------------------------------------------------------
// merged preprocessing (R14 verbatim)
// ---------------------------------------------------------------------------
#define NX4  ((S_LEN * EDIM) / 4)
#define NWQ4 ((QKVN * EDIM) / 4)
#define NWO4 ((EDIM * EDIM) / 4)
#define R4   (EDIM / 4)

__global__ void prep_kernel(const float4* __restrict__ x, __half2* __restrict__ xhi,
                            const float4* __restrict__ wq, __half2* __restrict__ wqh,
                            const float4* __restrict__ wo, __half2* __restrict__ woh,
                            const float* __restrict__ bq, float* __restrict__ bqp)
{
    int i = blockIdx.x * blockDim.x + threadIdx.x;
    if (i < NX4) {
        float4 v = x[i];
        xhi[2*i]   = __floats2half2_rn(v.x, v.y);
        xhi[2*i+1] = __floats2half2_rn(v.z, v.w);
    } else if (i < NX4 + NWQ4) {
        int j = i - NX4;
        int c = j / R4;
        int ic = j % R4;
        int h = c / 192, t = (c % 192) / 64, d = c % 64;
        int cp = t * EDIM + h * 64 + d;
        float4 v = wq[j];
        int o = cp * R4 + ic;
        wqh[2*o]   = __floats2half2_rn(v.x, v.y);
        wqh[2*o+1] = __floats2half2_rn(v.z, v.w);
    } else if (i < NX4 + NWQ4 + NWO4) {
        int j = i - NX4 - NWQ4;
        float4 v = wo[j];
        woh[2*j]   = __floats2half2_rn(v.x, v.y);
        woh[2*j+1] = __floats2half2_rn(v.z, v.w);
    } else if (i < NX4 + NWQ4 + NWO4 + QKVN) {
        int c = i - NX4 - NWQ4 - NWO4;
        int h = c / 192, t = (c % 192) / 64, d = c % 64;
        bqp[t * EDIM + h * 64 + d] = bq[c];
    }
}

// ---------------------------------------------------------------------------
// GEMM1 (1-pass BK=32): 128x128 CTA, 8 warps, warp 64x32.
// ---------------------------------------------------------------------------
#define TILE_BYTES 16384
#define STAGE_BYTES (2 * TILE_BYTES)
#define NSTAGE 3
#define GEMM_SMEM (NSTAGE * STAGE_BYTES + 1024)

__global__ __launch_bounds__(256, 2) void gemm_tc_kernel(
    const __half* __restrict__ Ahi,
    const __half* __restrict__ Bhi,
    const float* __restrict__ bias,
    __half* __restrict__ Chi,
    int M, int N, int K)
{
    extern __shared__ char smem[];
    const uint32_t sraw = smem_u32(smem);
    const uint32_t sbase = (sraw + 1023u) & ~1023u;

    const int tid  = threadIdx.x;
    const int wid  = tid >> 5;
    const int lane = tid & 31;
    const int bm = blockIdx.y * 128;
    const int bn = blockIdx.x * 128;
    const int nch = K >> 5;

    const int warp_m = wid & 1;
    const int warp_n = wid >> 1;

    const int lrow = tid >> 1;
    const int lsel = tid & 1;
    const uint32_t lsw = (uint32_t)((lrow & 7) << 4);
    const uint32_t lrowbase = (uint32_t)lrow * 128;
    const uint32_t lc0  = ((uint32_t)(2 * lsel) * 16) ^ lsw;
    const uint32_t lc1  = ((uint32_t)(2 * lsel + 1) * 16) ^ lsw;

    const __half* gah = Ahi + (size_t)(bm + lrow) * K + 2 * lsel * 8;
    const __half* gbh = Bhi + (size_t)(bn + lrow) * K + 2 * lsel * 8;

    float acc[4][4][4];
    #pragma unroll
    for (int i = 0; i < 4; i++)
        #pragma unroll
        for (int j = 0; j < 4; j++)
            #pragma unroll
            for (int e = 0; e < 4; e++) acc[i][j][e] = 0.f;

    auto load_stage = [&](int t, int buf) {
        const uint32_t sA = sbase + buf * STAGE_BYTES + lrowbase;
        const uint32_t sB = sA + TILE_BYTES;
        const int k0 = t * 32;
        CP_ASYNC16(sA + lc0, gah + k0);
        CP_ASYNC16(sA + lc1, gah + k0 + 8);
        CP_ASYNC16(sB + lc0, gbh + k0);
        CP_ASYNC16(sB + lc1, gbh + k0 + 8);
    };

    load_stage(0, 0); CP_COMMIT();
    load_stage(1, 1); CP_COMMIT();

    const int la_row = lane & 15;
    const int la_kh  = lane >> 4;
    const int lb_row = lane & 7;
    const int lb_kh  = (lane >> 3) & 1;

    uint32_t a_rowbase[4], a_sw[4];
    #pragma unroll
    for (int mi = 0; mi < 4; mi++) {
        const int row = warp_m * 64 + mi * 16 + la_row;
        a_rowbase[mi] = (uint32_t)row * 128;
        a_sw[mi] = (uint32_t)((row & 7) << 4);
    }
    uint32_t b_rowbase[4], b_sw[4];
    #pragma unroll
    for (int ni = 0; ni < 4; ni++) {
        const int row = warp_n * 32 + ni * 8 + lb_row;
        b_rowbase[ni] = (uint32_t)row * 128;
        b_sw[ni] = (uint32_t)((row & 7) << 4);
    }

    int buf = 0;
    for (int t = 0; t < nch; t++) {
        CP_WAIT1();
        __syncthreads();
        if (t + 2 < nch) {
            int b2 = buf + 2; if (b2 >= NSTAGE) b2 -= NSTAGE;
            load_stage(t + 2, b2);
        }
        CP_COMMIT();

        const uint32_t sA = sbase + buf * STAGE_BYTES;
        const uint32_t sB = sA + TILE_BYTES;

        #pragma unroll
        for (int ks = 0; ks < 2; ks++) {
            const uint32_t akoff = (uint32_t)(ks * 32 + la_kh * 16);
            const uint32_t bkoff = (uint32_t)(ks * 32 + lb_kh * 16);
            uint32_t bhv[4][2];
            #pragma unroll
            for (int ni = 0; ni < 4; ni++)
                ldsm_x2(bhv[ni], sB + b_rowbase[ni] + (bkoff ^ b_sw[ni]));
            #pragma unroll
            for (int mi = 0; mi < 4; mi++) {
                uint32_t ahi[4];
                ldsm_x4(ahi, sA + a_rowbase[mi] + (akoff ^ a_sw[mi]));
                #pragma unroll
                for (int ni = 0; ni < 4; ni++)
                    mma_f16(acc[mi][ni], ahi, bhv[ni]);
            }
        }
        buf++; if (buf >= NSTAGE) buf = 0;
    }

    #pragma unroll
    for (int mi = 0; mi < 4; mi++) {
        const int row = bm + warp_m * 64 + mi * 16 + (lane >> 2);
        #pragma unroll
        for (int ni = 0; ni < 4; ni++) {
            const int col = bn + warp_n * 32 + ni * 8 + (lane & 3) * 2;
            const float2 bv = *(const float2*)(bias + col);
            __half2 h0 = __floats2half2_rn(acc[mi][ni][0] + bv.x, acc[mi][ni][1] + bv.y);
            __half2 h1 = __floats2half2_rn(acc[mi][ni][2] + bv.x, acc[mi][ni][3] + bv.y);
            *(__half2*)(Chi + (size_t)row * N + col)       = h0;
            *(__half2*)(Chi + (size_t)(row + 8) * N + col) = h1;
        }
    }
}

// ---------------------------------------------------------------------------
// GEMM2 (1-pass BK=32): 64x128 CTA tile, 8 warps, warp 32x32.
// ---------------------------------------------------------------------------
#define G2_A_BYTES 8192
#define G2_STAGE   24576
#define G2_SMEM    (3 * G2_STAGE + 1024)

__global__ __launch_bounds__(256, 2) void gemm2_tc_kernel(
    const __half* __restrict__ Ahi,
    const __half* __restrict__ Bhi,
    const float* __restrict__ bias, float* __restrict__ C,
    int M, int N, int K)
{
    extern __shared__ char smem[];
    const uint32_t sraw = smem_u32(smem);
    const uint32_t sbase = (sraw + 1023u) & ~1023u;

    const int tid  = threadIdx.x;
    const int wid  = tid >> 5;
    const int lane = tid & 31;
    const int bm = blockIdx.y * 64;
    const int bn = blockIdx.x * 128;
    const int nch = K >> 5;

    const int warp_m = wid & 1;
    const int warp_n = wid >> 1;

    const int arow = tid >> 2;
    const int ac   = tid & 3;
    const uint32_t asw = (uint32_t)((arow & 7) << 4);
    const uint32_t arowbase = (uint32_t)arow * 128;
    const uint32_t aohi = ((uint32_t)(ac * 16)) ^ asw;
    const __half* gah = Ahi + (size_t)(bm + arow) * K + ac * 8;

    const int brow = tid >> 1;
    const int bc   = tid & 1;
    const uint32_t bsw = (uint32_t)((brow & 7) << 4);
    const uint32_t browbase = (uint32_t)brow * 128;
    const uint32_t bo0 = ((uint32_t)(2 * bc) * 16) ^ bsw;
    const uint32_t bo1 = ((uint32_t)(2 * bc + 1) * 16) ^ bsw;
    const __half* gbh = Bhi + (size_t)(bn + brow) * K + 2 * bc * 8;

    float acc[2][4][4];
    #pragma unroll
    for (int i = 0; i < 2; i++)
        #pragma unroll
        for (int j = 0; j < 4; j++)
            #pragma unroll
            for (int e = 0; e < 4; e++) acc[i][j][e] = 0.f;

    auto load_stage = [&](int t, int buf) {
        const int k0 = t * 32;
        const uint32_t sA = sbase + buf * G2_STAGE + arowbase;
        const uint32_t sB = sbase + buf * G2_STAGE + G2_A_BYTES + browbase;
        CP_ASYNC16(sA + aohi, gah + k0);
        CP_ASYNC16(sB + bo0,  gbh + k0);
        CP_ASYNC16(sB + bo1,  gbh + k0 + 8);
    };

    load_stage(0, 0); CP_COMMIT();
    load_stage(1, 1); CP_COMMIT();

    const int la_row = lane & 15;
    const int la_kh  = lane >> 4;
    const int lb_row = lane & 7;
    const int lb_kh  = (lane >> 3) & 1;

    uint32_t a_rowbase[2], a_sw2[2];
    #pragma unroll
    for (int mi = 0; mi < 2; mi++) {
        const int row = warp_m * 32 + mi * 16 + la_row;
        a_rowbase[mi] = (uint32_t)row * 128;
        a_sw2[mi] = (uint32_t)((row & 7) << 4);
    }
    uint32_t b_rowbase[4], b_sw2[4];
    #pragma unroll
    for (int ni = 0; ni < 4; ni++) {
        const int row = warp_n * 32 + ni * 8 + lb_row;
        b_rowbase[ni] = (uint32_t)(G2_A_BYTES + row * 128);
        b_sw2[ni] = (uint32_t)((row & 7) << 4);
    }

    int buf = 0;
    for (int t = 0; t < nch; t++) {
        CP_WAIT1();
        __syncthreads();
        if (t + 2 < nch) {
            int b2 = buf + 2; if (b2 >= 3) b2 -= 3;
            load_stage(t + 2, b2);
        }
        CP_COMMIT();

        const uint32_t sS = sbase + buf * G2_STAGE;

        #pragma unroll
        for (int ks = 0; ks < 2; ks++) {
            const uint32_t akoff = (uint32_t)(ks * 32 + la_kh * 16);
            const uint32_t bkoff = (uint32_t)(ks * 32 + lb_kh * 16);
            uint32_t bhv[4][2];
            #pragma unroll
            for (int ni = 0; ni < 4; ni++)
                ldsm_x2(bhv[ni], sS + b_rowbase[ni] + (bkoff ^ b_sw2[ni]));
            #pragma unroll
            for (int mi = 0; mi < 2; mi++) {
                uint32_t ahi[4];
                ldsm_x4(ahi, sS + a_rowbase[mi] + (akoff ^ a_sw2[mi]));
                #pragma unroll
                for (int ni = 0; ni < 4; ni++)
                    mma_f16(acc[mi][ni], ahi, bhv[ni]);
            }
        }
        buf++; if (buf >= 3) buf = 0;
    }

    #pragma unroll
    for (int mi = 0; mi < 2; mi++) {
        const int row = bm + warp_m * 32 + mi * 16 + (lane >> 2);
        #pragma unroll
        for (int ni = 0; ni < 4; ni++) {
            const int col = bn + warp_n * 32 + ni * 8 + (lane & 3) * 2;
            const float2 bv = *(const float2*)(bias + col);
            *(float2*)(C + (size_t)row * N + col) =
                make_float2(acc[mi][ni][0] + bv.x, acc[mi][ni][1] + bv.y);
            *(float2*)(C + (size_t)(row + 8) * N + col) =
                make_float2(acc[mi][ni][2] + bv.x, acc[mi][ni][3] + bv.y);
        }
    }
}

// ---------------------------------------------------------------------------
// Flash attention: QK 1-pass, PV 1-pass (p_hi only). 64-q CTA, 4 warps,
// cp.async double-buffered K/V prefetch.
// ---------------------------------------------------------------------------
#define QPITCH 72
#define SQHI 0
#define SKV0 9216
#define KVBUF 18432
#define ATTN_SMEM 46080

__global__ __launch_bounds__(128) void attn_tc_kernel(
    const __half* __restrict__ qkvhi, __half* __restrict__ ahi)
{
    extern __shared__ char smem[];
    const uint32_t sb = smem_u32(smem);

    const int tid  = threadIdx.x;
    const int lane = tid & 31;
    const int wq   = tid >> 5;
    const int h    = blockIdx.y;
    const int q0   = blockIdx.x * 64;

    const int lrow = tid >> 1;
    const int half = tid & 1;
    const uint32_t soff = (uint32_t)(lrow * QPITCH + half * 32) * 2;

    {
        const __half* sh = qkvhi + (size_t)(q0 + lrow) * QKVN + h * 64 + half * 32;
        #pragma unroll
        for (int i = 0; i < 4; i++)
            *(uint4*)(smem + SQHI + soff + i * 16) = *(const uint4*)(sh + i * 8);
    }

    auto kv_load = [&](int kb, int buf) {
        const int g = q0 - WIN + kb * 64 + lrow;
        const bool v = (g >= 0) && (g < S_LEN);
        const size_t gb = (size_t)(v ? g : 0) * QKVN + 768 + h * 64 + half * 32;
        const unsigned sz = v ? 16u : 0u;
        const uint32_t sk = sb + SKV0 + (uint32_t)buf * KVBUF + soff;
        const uint32_t sv = sk + 9216;
        #pragma unroll
        for (int i = 0; i < 4; i++) {
            CP_ASYNC16Z(sk + i * 16, qkvhi + gb + i * 8, sz);
            CP_ASYNC16Z(sv + i * 16, qkvhi + gb + 768 + i * 8, sz);
        }
    };

    kv_load(0, 0); CP_COMMIT();

    float oacc[8][4];
    #pragma unroll
    for (int ni = 0; ni < 8; ni++)
        #pragma unroll
        for (int e = 0; e < 4; e++) oacc[ni][e] = 0.f;
    float m_a = -1e30f, m_b = -1e30f, l_a = 0.f, l_b = 0.f;

    const int ra = q0 + wq * 16 + (lane >> 2);
    const int rb = ra + 8;

    for (int kb = 0; kb < 5; kb++) {
        const int jbase = q0 - WIN + kb * 64;
        if (kb + 1 < 5) {
            kv_load(kb + 1, (kb + 1) & 1);
            CP_COMMIT();
            CP_WAIT1();
        } else {
            CP_WAIT0();
        }
        __syncthreads();

        const uint32_t sk = sb + SKV0 + (uint32_t)(kb & 1) * KVBUF;
        const uint32_t sv = sk + 9216;

        float sacc[8][4];
        #pragma unroll
        for (int ni = 0; ni < 8; ni++)
            #pragma unroll
            for (int e = 0; e < 4; e++) sacc[ni][e] = 0.f;

        #pragma unroll
        for (int ks = 0; ks < 4; ks++) {
            uint32_t aqh[4];
            const uint32_t qoff = (uint32_t)((wq*16 + (lane & 15)) * QPITCH + ks*16 + (lane >> 4) * 8) * 2;
            ldsm_x4(aqh, sb + SQHI + qoff);
            #pragma unroll
            for (int ni = 0; ni < 8; ni++) {
                uint32_t bh[2];
                const uint32_t koff = (uint32_t)((ni*8 + (lane & 7)) * QPITCH + ks*16 + ((lane >> 3) & 1) * 8) * 2;
                ldsm_x2(bh, sk + koff);
                mma_f16(sacc[ni], aqh, bh);
            }
        }

        float mk_a = -1e30f, mk_b = -1e30f;
        #pragma unroll
        for (int ni = 0; ni < 8; ni++) {
            const int j0 = jbase + ni * 8 + (lane & 3) * 2;
            #pragma unroll
            for (int e = 0; e < 4; e++) {
                const int g = j0 + (e & 1);
                const int r = (e < 2) ? ra : rb;
                const int d = r - g;
                const bool ok = (g >= 0) && (g < S_LEN) && (d <= WIN) && (d >= -WIN);
                const float s = ok ? sacc[ni][e] * 0.125f : -1e30f;
                sacc[ni][e] = s;
                if (e < 2) mk_a = fmaxf(mk_a, s); else mk_b = fmaxf(mk_b, s);
            }
        }
        mk_a = fmaxf(mk_a, __shfl_xor_sync(0xffffffffu, mk_a, 1));
        mk_a = fmaxf(mk_a, __shfl_xor_sync(0xffffffffu, mk_a, 2));
        mk_b = fmaxf(mk_b, __shfl_xor_sync(0xffffffffu, mk_b, 1));
        mk_b = fmaxf(mk_b, __shfl_xor_sync(0xffffffffu, mk_b, 2));

        const float mn_a = fmaxf(m_a, mk_a);
        const float mn_b = fmaxf(m_b, mk_b);
        const float corr_a = __expf(m_a - mn_a);
        const float corr_b = __expf(m_b - mn_b);
        const float sm_a = (mn_a < -1e29f) ? 0.f : mn_a;
        const float sm_b = (mn_b < -1e29f) ? 0.f : mn_b;

        float su_a = 0.f, su_b = 0.f;
        #pragma unroll
        for (int ni = 0; ni < 8; ni++) {
            #pragma unroll
            for (int e = 0; e < 4; e++) {
                const float p = __expf(sacc[ni][e] - ((e < 2) ? sm_a : sm_b));
                sacc[ni][e] = p;
                if (e < 2) su_a += p; else su_b += p;
            }
        }
        su_a += __shfl_xor_sync(0xffffffffu, su_a, 1);
        su_a += __shfl_xor_sync(0xffffffffu, su_a, 2);
        su_b += __shfl_xor_sync(0xffffffffu, su_b, 1);
        su_b += __shfl_xor_sync(0xffffffffu, su_b, 2);

        l_a = l_a * corr_a + su_a;
        l_b = l_b * corr_b + su_b;
        m_a = mn_a; m_b = mn_b;

        #pragma unroll
        for (int ni = 0; ni < 8; ni++) {
            oacc[ni][0] *= corr_a; oacc[ni][1] *= corr_a;
            oacc[ni][2] *= corr_b; oacc[ni][3] *= corr_b;
        }

        // ---- PV 1-pass: p truncated to fp16 ----
        #pragma unroll
        for (int kk = 0; kk < 4; kk++) {
            uint32_t aph[4];
            aph[0] = pack_h2(sacc[2*kk][0],   sacc[2*kk][1]);
            aph[1] = pack_h2(sacc[2*kk][2],   sacc[2*kk][3]);
            aph[2] = pack_h2(sacc[2*kk+1][0], sacc[2*kk+1][1]);
            aph[3] = pack_h2(sacc[2*kk+1][2], sacc[2*kk+1][3]);
            #pragma unroll
            for (int ni = 0; ni < 8; ni++) {
                uint32_t bvh[2];
                const uint32_t voff = (uint32_t)((kk*16 + (lane & 15)) * QPITCH + ni * 8) * 2;
                ldsm_x2_trans(bvh, sv + voff);
                mma_f16(oacc[ni], aph, bvh);
            }
        }
        __syncthreads();
    }

    const float inv_a = (l_a > 0.f) ? 1.f / l_a : 0.f;
    const float inv_b = (l_b > 0.f) ? 1.f / l_b : 0.f;
    #pragma unroll
    for (int ni = 0; ni < 8; ni++) {
        const int d = h * 64 + ni * 8 + (lane & 3) * 2;
        __half2 o0 = __floats2half2_rn(oacc[ni][0] * inv_a, oacc[ni][1] * inv_a);
        __half2 o1 = __floats2half2_rn(oacc[ni][2] * inv_b, oacc[ni][3] * inv_b);
        *(__half2*)(ahi + (size_t)ra * EDIM + d) = o0;
        *(__half2*)(ahi + (size_t)rb * EDIM + d) = o1;
    }
}

// ---------------------------------------------------------------------------
extern "C" void kernel_launch(void* const* d_in, const int* in_sizes, int n_in,
                              void* d_out, int out_size)
{
    const float* x    = (const float*)d_in[0];
    const float* Wqkv = (const float*)d_in[1];
    const float* bqkv = (const float*)d_in[2];
    const float* Wo   = (const float*)d_in[3];
    const float* bo   = (const float*)d_in[4];
    float* out = (float*)d_out;

    __half *xhi, *wqh, *woh, *qkvhi, *ahi;
    float *bqp;
    cudaGetSymbolAddress((void**)&xhi,   g_xhi);
    cudaGetSymbolAddress((void**)&wqh,   g_wqh);
    cudaGetSymbolAddress((void**)&woh,   g_woh);
    cudaGetSymbolAddress((void**)&bqp,   g_bqp);
    cudaGetSymbolAddress((void**)&qkvhi, g_qkvhi);
    cudaGetSymbolAddress((void**)&ahi,   g_ahi);

    cudaFuncSetAttribute(gemm_tc_kernel,  cudaFuncAttributeMaxDynamicSharedMemorySize, GEMM_SMEM);
    cudaFuncSetAttribute(gemm2_tc_kernel, cudaFuncAttributeMaxDynamicSharedMemorySize, G2_SMEM);
    cudaFuncSetAttribute(attn_tc_kernel,  cudaFuncAttributeMaxDynamicSharedMemorySize, ATTN_SMEM);

    // 0) merged preprocessing
    {
        int ntot = NX4 + NWQ4 + NWO4 + QKVN;
        prep_kernel<<<(ntot + 255) / 256, 256>>>(
            (const float4*)x, (__half2*)xhi,
            (const float4*)Wqkv, (__half2*)wqh,
            (const float4*)Wo, (__half2*)woh,
            bqkv, bqp);
    }

    // 1) QKV projection (1-pass, BK=32) -> [Q|K|V] fp16
    gemm_tc_kernel<<<dim3(QKVN / 128, S_LEN / 128), 256, GEMM_SMEM>>>(
        xhi, wqh, bqp, qkvhi, S_LEN, QKVN, EDIM);

    // 2) flash attention (QK 1-pass, PV 1-pass) -> a_hi
    attn_tc_kernel<<<dim3(S_LEN / 64, NH), 128, ATTN_SMEM>>>(qkvhi, ahi);

    // 3) output projection (1-pass, BK=32) -> fp32 out
    gemm2_tc_kernel<<<dim3(EDIM / 128, S_LEN / 64), 256, G2_SMEM>>>(
        ahi, woh, bo, out, S_LEN, EDIM, EDIM);
}